// round 11
// baseline (speedup 1.0000x reference)
#include <cuda_runtime.h>
#include <cuda_fp16.h>
#include <math.h>

#define PP 20000
#define TT 30
#define SS 1000
#define DD 128     // elem embedding dim
#define HH 128     // LSTM hidden
#define GG 512     // 4*H gate width
#define DPP 128    // proj out dim
#define EE 64      // leaf embedding dim
#define VNT 10000
#define VLEAF 30000

// ---------------- device scratch (static: no allocations allowed) ----------
__device__ __half g_Hh[2][2][PP * HH];        // [dir][parity] hidden fp16, PERMUTED
__device__ float  g_Cst[2][PP * HH];          // [dir] cell fp32, PERMUTED
__device__ __half g_BwH[2][128 * GG];         // fp16 W, cols permuted m=4j+q, packed (k>>1)*1024+m*2+(k&1)
__device__ __half g_BuH[2][128 * GG];         // fp16 U, same packing
__device__ float  g_TW[2][(size_t)VNT * GG];  // TW[v][m] = emb[v]@W[:,m] + bias[m]  (permuted m)
__device__ __half g_embH[VNT * DD];           // fp16 element embeddings
__device__ __half g_leafH[VLEAF * EE];        // fp16 leaf embeddings
__device__ __half g_projH[384 * DPP];         // fp16 proj, packed (k>>1)*256 + n*2 + (k&1)
__device__ float  g_full[(size_t)PP * DPP];   // PERMUTED
__device__ float  g_scores[PP];               // PERMUTED
__device__ int    g_mxe[SS];
__device__ float  g_den[SS];
__device__ int    g_is64[2];
__device__ int    g_hist[TT + 2];
__device__ int    g_off[TT + 2];
__device__ int    g_perm[PP];                 // permuted row -> original path
__device__ int    g_cnt[TT];                  // #paths with len > s

// ---------------- helpers --------------------------------------------------
__device__ __forceinline__ int encf(float f) {
    int i = __float_as_int(f);
    return i >= 0 ? i : (i ^ 0x7fffffff);
}
__device__ __forceinline__ float decf(int i) {
    return __int_as_float(i >= 0 ? i : (i ^ 0x7fffffff));
}
__device__ __forceinline__ void mma_f16(float* c, const unsigned* a, const unsigned* b) {
    asm volatile(
        "mma.sync.aligned.m16n8k16.row.col.f32.f16.f16.f32 "
        "{%0,%1,%2,%3}, {%4,%5,%6,%7}, {%8,%9}, {%0,%1,%2,%3};"
        : "+f"(c[0]), "+f"(c[1]), "+f"(c[2]), "+f"(c[3])
        : "r"(a[0]), "r"(a[1]), "r"(a[2]), "r"(a[3]), "r"(b[0]), "r"(b[1]));
}
__device__ __forceinline__ float sigfast(float x) {
    return __fdividef(1.f, 1.f + __expf(-x));
}
__device__ __forceinline__ float tanhfast(float x) {
    return __fdividef(2.f, 1.f + __expf(-2.f * x)) - 1.f;
}
__device__ __forceinline__ void cpa16(void* smem, const void* g) {
    unsigned saddr = (unsigned)__cvta_generic_to_shared(smem);
    asm volatile("cp.async.cg.shared.global [%0], [%1], 16;" :: "r"(saddr), "l"(g));
}
__device__ __forceinline__ void cpa_commit() {
    asm volatile("cp.async.commit_group;" ::: "memory");
}

// ---------------- init + dtype detection -----------------------------------
__global__ void init_kernel(const void* pe, const void* li, float* out) {
    long long i = (long long)blockIdx.x * blockDim.x + threadIdx.x;
    const long long NHW = 2LL * PP * HH;            // 4 half buffers as uints
    if (i < NHW) ((unsigned*)g_Hh)[i] = 0u;
    long long j = i - NHW;
    if (j >= 0 && j < 2LL * PP * HH) (&g_Cst[0][0])[j] = 0.f;
    j -= 2LL * PP * HH;
    if (j >= 0 && j < PP) g_scores[j] = 0.f;
    j -= PP;
    if (j >= 0 && j < SS) {
        g_den[j] = 0.f;
        g_mxe[j] = (int)0x80000000;
    }
    j -= SS;
    if (j >= 0 && j < (long long)SS * DPP) out[j] = 0.f;
    j -= (long long)SS * DPP;
    if (j >= 0 && j < TT + 2) g_hist[j] = 0;

    if (i == 0) {
        int a = 1, b = 1;
        const int* p32 = (const int*)pe;
        const int* l32 = (const int*)li;
        for (int k = 0; k < 64; k++) {
            if (p32[2 * k + 1] != 0) a = 0;
            if (l32[2 * k + 1] != 0) b = 0;
        }
        g_is64[0] = a;
        g_is64[1] = b;
    }
}

// ---------------- counting sort by length (descending) ----------------------
__global__ void hist_k(const int* __restrict__ lens) {
    int p = blockIdx.x * 256 + threadIdx.x;
    if (p < PP) {
        int L = lens[p];
        if (L < 0) L = 0;
        if (L > TT) L = TT;
        atomicAdd(&g_hist[L], 1);
    }
}
__global__ void scan_k() {
    if (threadIdx.x == 0 && blockIdx.x == 0) {
        int run = 0;
        for (int L = TT; L >= 0; --L) {
            g_off[L] = run;
            run += g_hist[L];
        }
        for (int s = 0; s < TT; s++) {
            int c = 0;
            for (int L = s + 1; L <= TT; L++) c += g_hist[L];
            g_cnt[s] = c;
        }
    }
}
__global__ void scatter_k(const int* __restrict__ lens) {
    int p = blockIdx.x * 256 + threadIdx.x;
    if (p < PP) {
        int L = lens[p];
        if (L < 0) L = 0;
        if (L > TT) L = TT;
        int slot = atomicAdd(&g_off[L], 1);
        g_perm[slot] = p;
    }
}

// ---------------- convert weights/tables to fp16 ----------------------------
// new col m = 4*j + q maps to original col q*128 + j; packed k-pairs.
__global__ void bround_k(const float* __restrict__ Wf, const float* __restrict__ Uf,
                         const float* __restrict__ Wb, const float* __restrict__ Ub,
                         const float* __restrict__ emb, const float* __restrict__ leafE,
                         const float* __restrict__ proj)
{
    long long i = (long long)blockIdx.x * 256 + threadIdx.x;
    const long long NW = 2LL * 128 * GG;
    if (i < NW) {                                 // W tables
        int dir = (int)(i / (128 * GG));
        int r = (int)(i - (long long)dir * (128 * GG));
        int k = r / GG, m = r - k * GG;
        int oc = (m & 3) * 128 + (m >> 2);
        const float* W = dir ? Wb : Wf;
        g_BwH[dir][(size_t)(k >> 1) * 1024 + m * 2 + (k & 1)] =
            __float2half_rn(W[(size_t)k * GG + oc]);
        return;
    }
    long long j = i - NW;
    if (j < NW) {                                 // U tables
        int dir = (int)(j / (128 * GG));
        int r = (int)(j - (long long)dir * (128 * GG));
        int k = r / GG, m = r - k * GG;
        int oc = (m & 3) * 128 + (m >> 2);
        const float* U = dir ? Ub : Uf;
        g_BuH[dir][(size_t)(k >> 1) * 1024 + m * 2 + (k & 1)] =
            __float2half_rn(U[(size_t)k * GG + oc]);
        return;
    }
    j -= NW;
    if (j < (long long)VNT * DD) { g_embH[j] = __float2half_rn(emb[j]); return; }
    j -= (long long)VNT * DD;
    if (j < (long long)VLEAF * EE) { g_leafH[j] = __float2half_rn(leafE[j]); return; }
    j -= (long long)VLEAF * EE;
    if (j < 384 * DPP) {
        int k = (int)(j / DPP), n = (int)(j - (long long)k * DPP);
        g_projH[(size_t)(k >> 1) * 256 + n * 2 + (k & 1)] = __float2half_rn(proj[j]);
    }
}

// ---------------- TW precompute: TW[v][m] = emb[v]@W[:,m] + bias[m] ---------
// grid (79, 4, 2), 256 thr; fp16 mma over K=128; fp32 out, permuted cols.
__global__ __launch_bounds__(256, 2) void tw_k(
    const float* __restrict__ bf, const float* __restrict__ bb)
{
    const int dir = blockIdx.z;
    const int n0  = blockIdx.y * 128;
    const int v0  = blockIdx.x * 128;
    const int tid = threadIdx.x;
    const float* bias = dir ? bb : bf;
    const __half* __restrict__ BwH = g_BwH[dir];
    float* __restrict__ TWd = g_TW[dir];

    __shared__ __align__(16) __half AsH[128][40];
    __shared__ __align__(16) __half BsH[16][264];
    __shared__ float sBias[128];
    if (tid < 128)
        sBias[tid] = bias[(tid >> 5) * 128 + (n0 >> 2) + (tid & 31)];
    __syncthreads();

    const int warp = tid >> 5, lane = tid & 31;
    const int grp = lane >> 2, tig = lane & 3;
    const int wm = warp >> 1, wn = warp & 1;

    float acc[2][8][4];
#pragma unroll
    for (int m2 = 0; m2 < 2; m2++)
#pragma unroll
        for (int nt = 0; nt < 8; nt++)
#pragma unroll
            for (int q = 0; q < 4; q++) acc[m2][nt][q] = 0.f;

    for (int ck = 0; ck < 4; ck++) {
#pragma unroll
        for (int it = 0; it < 2; it++) {
            int idx = tid + it * 256;
            int r = idx >> 2, kh = (idx & 3) * 8;
            int v = v0 + r; if (v >= VNT) v = VNT - 1;
            *(uint4*)&AsH[r][kh] = *(const uint4*)&g_embH[(size_t)v * DD + ck * 32 + kh];
        }
#pragma unroll
        for (int it = 0; it < 2; it++) {
            int idx = tid + it * 256;
            int k2 = idx >> 5, h8 = (idx & 31) * 8;
            *(uint4*)&BsH[k2][h8] =
                *(const uint4*)&BwH[(size_t)(ck * 16 + k2) * 1024 + n0 * 2 + h8];
        }
        __syncthreads();
#pragma unroll
        for (int km = 0; km < 2; km++) {
            const int kb = km * 16;
            unsigned a[2][4], b[8][2];
#pragma unroll
            for (int m2 = 0; m2 < 2; m2++) {
                int rb = wm * 32 + m2 * 16;
                a[m2][0] = *(const unsigned*)&AsH[rb + grp][kb + 2 * tig];
                a[m2][1] = *(const unsigned*)&AsH[rb + grp + 8][kb + 2 * tig];
                a[m2][2] = *(const unsigned*)&AsH[rb + grp][kb + 2 * tig + 8];
                a[m2][3] = *(const unsigned*)&AsH[rb + grp + 8][kb + 2 * tig + 8];
            }
#pragma unroll
            for (int nt = 0; nt < 8; nt++) {
                int cb = wn * 64 + nt * 8 + grp;
                b[nt][0] = *(const unsigned*)&BsH[km * 8 + tig][cb * 2];
                b[nt][1] = *(const unsigned*)&BsH[km * 8 + tig + 4][cb * 2];
            }
#pragma unroll
            for (int m2 = 0; m2 < 2; m2++)
#pragma unroll
                for (int nt = 0; nt < 8; nt++)
                    mma_f16(acc[m2][nt], a[m2], b[nt]);
        }
        __syncthreads();
    }

#pragma unroll
    for (int m2 = 0; m2 < 2; m2++) {
        int rl = wm * 32 + m2 * 16 + grp;
        int vA = v0 + rl;     if (vA >= VNT) vA = VNT - 1;
        int vB = v0 + rl + 8; if (vB >= VNT) vB = VNT - 1;
#pragma unroll
        for (int nt = 0; nt < 8; nt++) {
            int mcol = n0 + wn * 64 + nt * 8 + tig * 2;
            int jloc = wn * 16 + nt * 2 + (tig >> 1);
            int q = mcol & 3;
            float b0 = sBias[q * 32 + jloc], b1 = sBias[(q + 1) * 32 + jloc];
            *(float2*)&TWd[(size_t)vA * GG + mcol] =
                make_float2(acc[m2][nt][0] + b0, acc[m2][nt][1] + b1);
            *(float2*)&TWd[(size_t)vB * GG + mcol] =
                make_float2(acc[m2][nt][2] + b0, acc[m2][nt][3] + b1);
        }
    }
}

// ---------------- fused LSTM step: z = h@U (mma) + TW acc-init + gates ------
// grid (157, 4, 2), 256 thr = 8 warps (4M x 2N), C tile 128x128 of permuted z.
// acc initialized from TW[e] (overlapped with cp.async); C prefetched via
// cp.async group 0; gate epilogue reads smem-resident C with no global stall.
__global__ __launch_bounds__(256, 2) void lstm_step(
    const void* __restrict__ pe, int t)
{
    const int dir = blockIdx.z;
    const int s   = dir ? (TT - 1 - t) : t;
    const int cnt = g_cnt[s];
    const int p0  = blockIdx.x * 128;
    if (p0 >= cnt) return;
    const int n0  = blockIdx.y * 128;
    const int tid = threadIdx.x;

    __shared__ __align__(16) char smx[56320];
    __half (*AsH)[128][40] = (__half(*)[128][40])(smx);           // 20480 B
    __half (*BsH)[16][264] = (__half(*)[16][264])(smx + 20480);   // 16896 B
    int*   sE    = (int*)  (smx + 37376);                         // 512 B
    float (*Cs)[36] = (float(*)[36])(smx + 37888);                // 18432 B

    const __half* __restrict__ HoldH = g_Hh[dir][t & 1];
    __half* __restrict__ HnewH = g_Hh[dir][(t + 1) & 1];
    float* __restrict__ Cd   = g_Cst[dir];
    const __half* __restrict__ BuH = g_BuH[dir];
    const float* __restrict__ TWd = g_TW[dir];
    const int jcol0 = n0 >> 2;

    int nact = cnt - p0;
    if (nact > 128) nact = 128;

    if (tid < 128) {
        int p = p0 + tid;
        if (p >= PP) p = PP - 1;
        int orig = g_perm[p];
        long long e;
        if (g_is64[0]) e = ((const long long*)pe)[(long long)orig * TT + s];
        else           e = ((const int*)pe)[orig * TT + s];
        sE[tid] = (int)e;
    }
    __syncthreads();

    const int warp = tid >> 5, lane = tid & 31;
    const int grp = lane >> 2, tig = lane & 3;
    const int wm = warp >> 1, wn = warp & 1;

    // ---- stage issuer: k-chunk ck (32 k of the h@U GEMM) into stage sb ----
    auto issue = [&](int ck, int sb) {
#pragma unroll
        for (int it = 0; it < 2; it++) {
            int idx = tid + it * 256;
            int r = idx >> 2, kh = (idx & 3) * 8;
            int p = p0 + r;
            if (p >= PP) p = PP - 1;
            cpa16(&AsH[sb][r][kh], &HoldH[(size_t)p * HH + ck * 32 + kh]);
        }
#pragma unroll
        for (int it = 0; it < 2; it++) {
            int idx = tid + it * 256;
            int k2 = idx >> 5, h8 = (idx & 31) * 8;
            cpa16(&BsH[sb][k2][h8],
                  &BuH[(size_t)(ck * 16 + k2) * 1024 + n0 * 2 + h8]);
        }
    };

    // ---- group 0: chunk 0 + C-state prefetch ----
#pragma unroll
    for (int it = 0; it < 4; it++) {
        int i4 = tid + it * 256;
        int r = i4 >> 3, c4 = (i4 & 7) * 4;
        if (r < nact)
            cpa16(&Cs[r][c4], &Cd[(size_t)(p0 + r) * HH + jcol0 + c4]);
    }
    issue(0, 0);
    cpa_commit();

    // ---- acc init from TW (x@W + bias), overlapped with cp.async flight ----
    float acc[2][8][4];
#pragma unroll
    for (int m2 = 0; m2 < 2; m2++) {
        int rlA = wm * 32 + m2 * 16 + grp;
        size_t eA = (size_t)sE[rlA] * GG;
        size_t eB = (size_t)sE[rlA + 8] * GG;
#pragma unroll
        for (int nt = 0; nt < 8; nt++) {
            int mcol = n0 + wn * 64 + nt * 8 + tig * 2;
            float2 tA = *(const float2*)&TWd[eA + mcol];
            float2 tB = *(const float2*)&TWd[eB + mcol];
            acc[m2][nt][0] = tA.x; acc[m2][nt][1] = tA.y;
            acc[m2][nt][2] = tB.x; acc[m2][nt][3] = tB.y;
        }
    }

    for (int ck = 0; ck < 4; ck++) {
        const int sb = ck & 1;
        if (ck < 3) {
            issue(ck + 1, sb ^ 1);
            cpa_commit();
            asm volatile("cp.async.wait_group 1;" ::: "memory");
        } else {
            asm volatile("cp.async.wait_group 0;" ::: "memory");
        }
        __syncthreads();

#pragma unroll
        for (int km = 0; km < 2; km++) {
            const int kb = km * 16;
            unsigned a[2][4], b[8][2];
#pragma unroll
            for (int m2 = 0; m2 < 2; m2++) {
                int rb = wm * 32 + m2 * 16;
                a[m2][0] = *(const unsigned*)&AsH[sb][rb + grp][kb + 2 * tig];
                a[m2][1] = *(const unsigned*)&AsH[sb][rb + grp + 8][kb + 2 * tig];
                a[m2][2] = *(const unsigned*)&AsH[sb][rb + grp][kb + 2 * tig + 8];
                a[m2][3] = *(const unsigned*)&AsH[sb][rb + grp + 8][kb + 2 * tig + 8];
            }
#pragma unroll
            for (int nt = 0; nt < 8; nt++) {
                int cb = wn * 64 + nt * 8 + grp;
                b[nt][0] = *(const unsigned*)&BsH[sb][km * 8 + tig][cb * 2];
                b[nt][1] = *(const unsigned*)&BsH[sb][km * 8 + tig + 4][cb * 2];
            }
#pragma unroll
            for (int m2 = 0; m2 < 2; m2++)
#pragma unroll
                for (int nt = 0; nt < 8; nt++)
                    mma_f16(acc[m2][nt], a[m2], b[nt]);
        }
        __syncthreads();
    }

    // ---- fused gate epilogue: C already smem-resident; Hs aliases AsH ----
    float (*Hs)[36] = (float(*)[36])(smx);   // 18432 B over the 20480 B AsH region

#pragma unroll
    for (int m2 = 0; m2 < 2; m2++) {
        int rl = wm * 32 + m2 * 16 + grp;
#pragma unroll
        for (int nt = 0; nt < 8; nt++) {
            float c0 = acc[m2][nt][0], c1 = acc[m2][nt][1];
            float c2 = acc[m2][nt][2], c3 = acc[m2][nt][3];
            float s0 = (tig & 1) ? c0 : c2;
            float s1 = (tig & 1) ? c1 : c3;
            float r0 = __shfl_xor_sync(0xffffffff, s0, 1);
            float r1 = __shfl_xor_sync(0xffffffff, s1, 1);
            int rr; float zi, zf, zg, zo;
            if ((tig & 1) == 0) { rr = rl;     zi = c0; zf = c1; zg = r0; zo = r1; }
            else                { rr = rl + 8; zi = r0; zf = r1; zg = c2; zo = c3; }
            int jl = wn * 16 + nt * 2 + (tig >> 1);
            if (rr < nact) {
                float ig = sigfast(zi), fg = sigfast(zf);
                float gg = tanhfast(zg), og = sigfast(zo);
                float c  = Cs[rr][jl];
                float cn = fg * c + ig * gg;
                Cs[rr][jl] = cn;
                Hs[rr][jl] = og * tanhfast(cn);
            }
        }
    }
    __syncthreads();

    // coalesced write-out: C fp32, H fp16 (converted here)
#pragma unroll
    for (int it = 0; it < 4; it++) {
        int i4 = tid + it * 256;
        int r = i4 >> 3, c4 = (i4 & 7) * 4;
        if (r < nact)
            *(float4*)&Cd[(size_t)(p0 + r) * HH + jcol0 + c4] =
                *(const float4*)&Cs[r][c4];
    }
#pragma unroll
    for (int it = 0; it < 2; it++) {
        int i8 = tid + it * 256;
        int r = i8 >> 2, c8 = (i8 & 3) * 8;
        if (r < nact) {
            float4 v0 = *(const float4*)&Hs[r][c8];
            float4 v1 = *(const float4*)&Hs[r][c8 + 4];
            __half2 hh[4];
            hh[0] = __floats2half2_rn(v0.x, v0.y);
            hh[1] = __floats2half2_rn(v0.z, v0.w);
            hh[2] = __floats2half2_rn(v1.x, v1.y);
            hh[3] = __floats2half2_rn(v1.z, v1.w);
            *(uint4*)&HnewH[(size_t)(p0 + r) * HH + jcol0 + c8] = *(uint4*)hh;
        }
    }
}

// ---------------- proj GEMM (fp16 mma): full = [leaf|h_f|h_b] @ proj --------
__global__ __launch_bounds__(256, 2) void proj_mma(
    const void* __restrict__ li, const float* __restrict__ att,
    const int* __restrict__ lens)
{
    const int p0 = blockIdx.x * 128;
    const int tid = threadIdx.x;
    __shared__ __align__(16) __half AsH[128][40];
    __shared__ __align__(16) __half BsH[16][264];
    __shared__ int   sL[128][2];
    __shared__ int   sBuf[128];
    __shared__ float sAtt[128];

    {
        int r = tid >> 1, which = tid & 1;
        int p = p0 + r;
        if (p >= PP) p = PP - 1;
        int orig = g_perm[p];
        long long v;
        if (g_is64[1]) v = ((const long long*)li)[(long long)orig * 2 + which];
        else           v = ((const int*)li)[orig * 2 + which];
        sL[r][which] = (int)v;
    }
    if (tid < 128) {
        int p = p0 + tid;
        if (p >= PP) p = PP - 1;
        int L = lens[g_perm[p]];
        if (L < 0) L = 0;
        sBuf[tid] = L & 1;
        sAtt[tid] = att[tid];
    }
    __syncthreads();

    const int warp = tid >> 5, lane = tid & 31;
    const int grp = lane >> 2, tig = lane & 3;
    const int wm = warp >> 1, wn = warp & 1;

    float acc[2][8][4];
#pragma unroll
    for (int mt = 0; mt < 2; mt++)
#pragma unroll
        for (int nt = 0; nt < 8; nt++)
#pragma unroll
            for (int q = 0; q < 4; q++) acc[mt][nt][q] = 0.f;

    for (int ck = 0; ck < 12; ck++) {      // K = 384
        const int k0 = ck * 32;
#pragma unroll
        for (int it = 0; it < 2; it++) {
            int idx = tid + it * 256;
            int r = idx >> 2, h8 = (idx & 3) * 8;
            int gk = k0 + h8;
            int p = p0 + r;
            if (p >= PP) p = PP - 1;
            const __half* src;
            if (gk < 64)       src = &g_leafH[(size_t)sL[r][0] * EE + gk];
            else if (gk < 128) src = &g_leafH[(size_t)sL[r][1] * EE + (gk - 64)];
            else if (gk < 256) src = &g_Hh[0][sBuf[r]][(size_t)p * HH + (gk - 128)];
            else               src = &g_Hh[1][0][(size_t)p * HH + (gk - 256)];
            *(uint4*)&AsH[r][h8] = *(const uint4*)src;
        }
#pragma unroll
        for (int it = 0; it < 2; it++) {
            int idx = tid + it * 256;
            int k2 = idx >> 5, h8 = (idx & 31) * 8;
            *(uint4*)&BsH[k2][h8] =
                *(const uint4*)&g_projH[(size_t)(ck * 16 + k2) * 256 + h8];
        }
        __syncthreads();

#pragma unroll
        for (int km = 0; km < 2; km++) {
            const int kb = km * 16;
            unsigned a[2][4], b[8][2];
#pragma unroll
            for (int mt = 0; mt < 2; mt++) {
                int rb = wm * 32 + mt * 16;
                a[mt][0] = *(const unsigned*)&AsH[rb + grp][kb + 2 * tig];
                a[mt][1] = *(const unsigned*)&AsH[rb + grp + 8][kb + 2 * tig];
                a[mt][2] = *(const unsigned*)&AsH[rb + grp][kb + 2 * tig + 8];
                a[mt][3] = *(const unsigned*)&AsH[rb + grp + 8][kb + 2 * tig + 8];
            }
#pragma unroll
            for (int nt = 0; nt < 8; nt++) {
                int cb = wn * 64 + nt * 8 + grp;
                b[nt][0] = *(const unsigned*)&BsH[km * 8 + tig][cb * 2];
                b[nt][1] = *(const unsigned*)&BsH[km * 8 + tig + 4][cb * 2];
            }
#pragma unroll
            for (int mt = 0; mt < 2; mt++)
#pragma unroll
                for (int nt = 0; nt < 8; nt++)
                    mma_f16(acc[mt][nt], a[mt], b[nt]);
        }
        __syncthreads();
    }

    // epilogue: write g_full + fused score dot (full . att)
    float loc[4] = {0.f, 0.f, 0.f, 0.f};
#pragma unroll
    for (int mt = 0; mt < 2; mt++) {
        int pr = p0 + wm * 32 + mt * 16 + grp;
#pragma unroll
        for (int nt = 0; nt < 8; nt++) {
            int col = wn * 64 + nt * 8 + tig * 2;
            float a0 = sAtt[col], a1 = sAtt[col + 1];
            loc[mt * 2 + 0] += acc[mt][nt][0] * a0 + acc[mt][nt][1] * a1;
            loc[mt * 2 + 1] += acc[mt][nt][2] * a0 + acc[mt][nt][3] * a1;
            if (pr < PP)
                *(float2*)&g_full[(size_t)pr * DPP + col] =
                    make_float2(acc[mt][nt][0], acc[mt][nt][1]);
            if (pr + 8 < PP)
                *(float2*)&g_full[(size_t)(pr + 8) * DPP + col] =
                    make_float2(acc[mt][nt][2], acc[mt][nt][3]);
        }
    }
#pragma unroll
    for (int q = 0; q < 4; q++) {
        loc[q] += __shfl_xor_sync(0xffffffff, loc[q], 1);
        loc[q] += __shfl_xor_sync(0xffffffff, loc[q], 2);
    }
    if (tig == 0) {
#pragma unroll
        for (int mt = 0; mt < 2; mt++) {
            int pr = p0 + wm * 32 + mt * 16 + grp;
            if (pr < PP)     atomicAdd(&g_scores[pr], loc[mt * 2 + 0]);
            if (pr + 8 < PP) atomicAdd(&g_scores[pr + 8], loc[mt * 2 + 1]);
        }
    }
}

// ---------------- segment softmax + weighted accumulation ------------------
__global__ void seg_max_k(const int* __restrict__ seg) {
    int p = blockIdx.x * 256 + threadIdx.x;
    if (p < PP) atomicMax(&g_mxe[seg[g_perm[p]]], encf(g_scores[p]));
}
__global__ void seg_den_k(const int* __restrict__ seg) {
    int p = blockIdx.x * 256 + threadIdx.x;
    if (p < PP) {
        int s = seg[g_perm[p]];
        atomicAdd(&g_den[s], __expf(g_scores[p] - decf(g_mxe[s])));
    }
}
__global__ void seg_out_k(const int* __restrict__ seg, float* __restrict__ out) {
    int idx = blockIdx.x * 256 + threadIdx.x;
    if (idx < PP * DPP) {
        int p = idx >> 7, j = idx & 127;
        int s = seg[g_perm[p]];
        float w = __expf(g_scores[p] - decf(g_mxe[s])) / g_den[s];
        atomicAdd(&out[(size_t)s * DPP + j], w * g_full[idx]);
    }
}

// ---------------- launch ----------------------------------------------------
extern "C" void kernel_launch(void* const* d_in, const int* in_sizes, int n_in,
                              void* d_out, int out_size)
{
    (void)in_sizes; (void)n_in; (void)out_size;
    const float* leafE = (const float*)d_in[0];
    const float* emb   = (const float*)d_in[1];
    const float* Wf    = (const float*)d_in[2];
    const float* Uf    = (const float*)d_in[3];
    const float* bf    = (const float*)d_in[4];
    const float* Wb    = (const float*)d_in[5];
    const float* Ub    = (const float*)d_in[6];
    const float* bb    = (const float*)d_in[7];
    const float* proj  = (const float*)d_in[8];
    const float* att   = (const float*)d_in[9];
    const void*  pe    = d_in[10];
    const int*   lens  = (const int*)d_in[11];
    const void*  li    = d_in[12];
    const int*   seg   = (const int*)d_in[13];
    float* out = (float*)d_out;

    const long long initN = 4LL * PP * HH + PP + SS + (long long)SS * DPP + TT + 2;
    init_kernel<<<(unsigned)((initN + 255) / 256), 256>>>(pe, li, out);
    hist_k<<<(PP + 255) / 256, 256>>>(lens);
    scan_k<<<1, 32>>>();
    scatter_k<<<(PP + 255) / 256, 256>>>(lens);
    const long long brN = 4LL * 128 * GG + (long long)VNT * DD
                        + (long long)VLEAF * EE + 384 * DPP;
    bround_k<<<(unsigned)((brN + 255) / 256), 256>>>(Wf, Uf, Wb, Ub, emb, leafE, proj);

    dim3 twgrid((VNT + 127) / 128, 4, 2);
    tw_k<<<twgrid, 256>>>(bf, bb);

    dim3 ggrid((PP + 127) / 128, 4, 2);
    for (int t = 0; t < TT; t++) {
        lstm_step<<<ggrid, 256>>>(pe, t);
    }
    proj_mma<<<(PP + 127) / 128, 256>>>(li, att, lens);
    seg_max_k<<<(PP + 255) / 256, 256>>>(seg);
    seg_den_k<<<(PP + 255) / 256, 256>>>(seg);
    seg_out_k<<<(PP * DPP + 255) / 256, 256>>>(seg, out);
}

// round 13
// speedup vs baseline: 1.5235x; 1.5235x over previous
#include <cuda_runtime.h>
#include <cuda_fp16.h>
#include <math.h>

#define PP 20000
#define TT 30
#define SS 1000
#define DD 128     // elem embedding dim
#define HH 128     // LSTM hidden
#define GG 512     // 4*H gate width
#define DPP 128    // proj out dim
#define EE 64      // leaf embedding dim
#define VNT 10000
#define VLEAF 30000

// ---------------- device scratch (static: no allocations allowed) ----------
__device__ __half g_Hh[2][2][PP * HH];        // [dir][parity] hidden fp16, PERMUTED
__device__ float  g_Cst[2][PP * HH];          // [dir] cell fp32, PERMUTED
__device__ __half g_BwH[2][128 * GG];         // fp16 W, cols permuted m=4j+q, packed (k>>1)*1024+m*2+(k&1)
__device__ __half g_BuH[2][128 * GG];         // fp16 U, same packing
__device__ float  g_TW[2][(size_t)VNT * GG];  // TW[v][m] = emb[v]@W[:,m] + bias[m]  (permuted m)
__device__ __half g_embH[VNT * DD];           // fp16 element embeddings
__device__ __half g_leafH[VLEAF * EE];        // fp16 leaf embeddings
__device__ __half g_projH[384 * DPP];         // fp16 proj, packed (k>>1)*256 + n*2 + (k&1)
__device__ float  g_full[(size_t)PP * DPP];   // PERMUTED
__device__ float  g_scores[PP];               // PERMUTED
__device__ int    g_mxe[SS];
__device__ float  g_den[SS];
__device__ int    g_is64[2];
__device__ int    g_hist[TT + 2];
__device__ int    g_off[TT + 2];
__device__ int    g_perm[PP];                 // permuted row -> original path
__device__ int    g_cnt[TT];                  // #paths with len > s

// ---------------- helpers --------------------------------------------------
__device__ __forceinline__ int encf(float f) {
    int i = __float_as_int(f);
    return i >= 0 ? i : (i ^ 0x7fffffff);
}
__device__ __forceinline__ float decf(int i) {
    return __int_as_float(i >= 0 ? i : (i ^ 0x7fffffff));
}
__device__ __forceinline__ void mma_f16(float* c, const unsigned* a, const unsigned* b) {
    asm volatile(
        "mma.sync.aligned.m16n8k16.row.col.f32.f16.f16.f32 "
        "{%0,%1,%2,%3}, {%4,%5,%6,%7}, {%8,%9}, {%0,%1,%2,%3};"
        : "+f"(c[0]), "+f"(c[1]), "+f"(c[2]), "+f"(c[3])
        : "r"(a[0]), "r"(a[1]), "r"(a[2]), "r"(a[3]), "r"(b[0]), "r"(b[1]));
}
__device__ __forceinline__ float sigfast(float x) {
    return __fdividef(1.f, 1.f + __expf(-x));
}
__device__ __forceinline__ float tanhfast(float x) {
    return __fdividef(2.f, 1.f + __expf(-2.f * x)) - 1.f;
}
__device__ __forceinline__ void cpa16(void* smem, const void* g) {
    unsigned saddr = (unsigned)__cvta_generic_to_shared(smem);
    asm volatile("cp.async.cg.shared.global [%0], [%1], 16;" :: "r"(saddr), "l"(g));
}
__device__ __forceinline__ void cpa_commit() {
    asm volatile("cp.async.commit_group;" ::: "memory");
}

// ---------------- init + dtype detection -----------------------------------
__global__ void init_kernel(const void* pe, const void* li, float* out) {
    long long i = (long long)blockIdx.x * blockDim.x + threadIdx.x;
    const long long NHW = 2LL * PP * HH;            // 4 half buffers as uints
    if (i < NHW) ((unsigned*)g_Hh)[i] = 0u;
    long long j = i - NHW;
    if (j >= 0 && j < 2LL * PP * HH) (&g_Cst[0][0])[j] = 0.f;
    j -= 2LL * PP * HH;
    if (j >= 0 && j < PP) g_scores[j] = 0.f;
    j -= PP;
    if (j >= 0 && j < SS) {
        g_den[j] = 0.f;
        g_mxe[j] = (int)0x80000000;
    }
    j -= SS;
    if (j >= 0 && j < (long long)SS * DPP) out[j] = 0.f;
    j -= (long long)SS * DPP;
    if (j >= 0 && j < TT + 2) g_hist[j] = 0;

    if (i == 0) {
        int a = 1, b = 1;
        const int* p32 = (const int*)pe;
        const int* l32 = (const int*)li;
        for (int k = 0; k < 64; k++) {
            if (p32[2 * k + 1] != 0) a = 0;
            if (l32[2 * k + 1] != 0) b = 0;
        }
        g_is64[0] = a;
        g_is64[1] = b;
    }
}

// ---------------- counting sort by length (descending) ----------------------
__global__ void hist_k(const int* __restrict__ lens) {
    int p = blockIdx.x * 256 + threadIdx.x;
    if (p < PP) {
        int L = lens[p];
        if (L < 0) L = 0;
        if (L > TT) L = TT;
        atomicAdd(&g_hist[L], 1);
    }
}
__global__ void scan_k() {
    if (threadIdx.x == 0 && blockIdx.x == 0) {
        int run = 0;
        for (int L = TT; L >= 0; --L) {
            g_off[L] = run;
            run += g_hist[L];
        }
        for (int s = 0; s < TT; s++) {
            int c = 0;
            for (int L = s + 1; L <= TT; L++) c += g_hist[L];
            g_cnt[s] = c;
        }
    }
}
__global__ void scatter_k(const int* __restrict__ lens) {
    int p = blockIdx.x * 256 + threadIdx.x;
    if (p < PP) {
        int L = lens[p];
        if (L < 0) L = 0;
        if (L > TT) L = TT;
        int slot = atomicAdd(&g_off[L], 1);
        g_perm[slot] = p;
    }
}

// ---------------- convert weights/tables to fp16 ----------------------------
// new col m = 4*j + q maps to original col q*128 + j; packed k-pairs.
__global__ void bround_k(const float* __restrict__ Wf, const float* __restrict__ Uf,
                         const float* __restrict__ Wb, const float* __restrict__ Ub,
                         const float* __restrict__ emb, const float* __restrict__ leafE,
                         const float* __restrict__ proj)
{
    long long i = (long long)blockIdx.x * 256 + threadIdx.x;
    const long long NW = 2LL * 128 * GG;
    if (i < NW) {                                 // W tables
        int dir = (int)(i / (128 * GG));
        int r = (int)(i - (long long)dir * (128 * GG));
        int k = r / GG, m = r - k * GG;
        int oc = (m & 3) * 128 + (m >> 2);
        const float* W = dir ? Wb : Wf;
        g_BwH[dir][(size_t)(k >> 1) * 1024 + m * 2 + (k & 1)] =
            __float2half_rn(W[(size_t)k * GG + oc]);
        return;
    }
    long long j = i - NW;
    if (j < NW) {                                 // U tables
        int dir = (int)(j / (128 * GG));
        int r = (int)(j - (long long)dir * (128 * GG));
        int k = r / GG, m = r - k * GG;
        int oc = (m & 3) * 128 + (m >> 2);
        const float* U = dir ? Ub : Uf;
        g_BuH[dir][(size_t)(k >> 1) * 1024 + m * 2 + (k & 1)] =
            __float2half_rn(U[(size_t)k * GG + oc]);
        return;
    }
    j -= NW;
    if (j < (long long)VNT * DD) { g_embH[j] = __float2half_rn(emb[j]); return; }
    j -= (long long)VNT * DD;
    if (j < (long long)VLEAF * EE) { g_leafH[j] = __float2half_rn(leafE[j]); return; }
    j -= (long long)VLEAF * EE;
    if (j < 384 * DPP) {
        int k = (int)(j / DPP), n = (int)(j - (long long)k * DPP);
        g_projH[(size_t)(k >> 1) * 256 + n * 2 + (k & 1)] = __float2half_rn(proj[j]);
    }
}

// ---------------- TW precompute: TW[v][m] = emb[v]@W[:,m] + bias[m] ---------
// grid (79, 4, 2), 256 thr; fp16 mma over K=128; fp32 out, permuted cols.
__global__ __launch_bounds__(256, 2) void tw_k(
    const float* __restrict__ bf, const float* __restrict__ bb)
{
    const int dir = blockIdx.z;
    const int n0  = blockIdx.y * 128;
    const int v0  = blockIdx.x * 128;
    const int tid = threadIdx.x;
    const float* bias = dir ? bb : bf;
    const __half* __restrict__ BwH = g_BwH[dir];
    float* __restrict__ TWd = g_TW[dir];

    __shared__ __align__(16) __half AsH[128][40];
    __shared__ __align__(16) __half BsH[16][264];
    __shared__ float sBias[128];
    if (tid < 128)
        sBias[tid] = bias[(tid >> 5) * 128 + (n0 >> 2) + (tid & 31)];
    __syncthreads();

    const int warp = tid >> 5, lane = tid & 31;
    const int grp = lane >> 2, tig = lane & 3;
    const int wm = warp >> 1, wn = warp & 1;

    float acc[2][8][4];
#pragma unroll
    for (int m2 = 0; m2 < 2; m2++)
#pragma unroll
        for (int nt = 0; nt < 8; nt++)
#pragma unroll
            for (int q = 0; q < 4; q++) acc[m2][nt][q] = 0.f;

    for (int ck = 0; ck < 4; ck++) {
#pragma unroll
        for (int it = 0; it < 2; it++) {
            int idx = tid + it * 256;
            int r = idx >> 2, kh = (idx & 3) * 8;
            int v = v0 + r; if (v >= VNT) v = VNT - 1;
            *(uint4*)&AsH[r][kh] = *(const uint4*)&g_embH[(size_t)v * DD + ck * 32 + kh];
        }
#pragma unroll
        for (int it = 0; it < 2; it++) {
            int idx = tid + it * 256;
            int k2 = idx >> 5, h8 = (idx & 31) * 8;
            *(uint4*)&BsH[k2][h8] =
                *(const uint4*)&BwH[(size_t)(ck * 16 + k2) * 1024 + n0 * 2 + h8];
        }
        __syncthreads();
#pragma unroll
        for (int km = 0; km < 2; km++) {
            const int kb = km * 16;
            unsigned a[2][4], b[8][2];
#pragma unroll
            for (int m2 = 0; m2 < 2; m2++) {
                int rb = wm * 32 + m2 * 16;
                a[m2][0] = *(const unsigned*)&AsH[rb + grp][kb + 2 * tig];
                a[m2][1] = *(const unsigned*)&AsH[rb + grp + 8][kb + 2 * tig];
                a[m2][2] = *(const unsigned*)&AsH[rb + grp][kb + 2 * tig + 8];
                a[m2][3] = *(const unsigned*)&AsH[rb + grp + 8][kb + 2 * tig + 8];
            }
#pragma unroll
            for (int nt = 0; nt < 8; nt++) {
                int cb = wn * 64 + nt * 8 + grp;
                b[nt][0] = *(const unsigned*)&BsH[km * 8 + tig][cb * 2];
                b[nt][1] = *(const unsigned*)&BsH[km * 8 + tig + 4][cb * 2];
            }
#pragma unroll
            for (int m2 = 0; m2 < 2; m2++)
#pragma unroll
                for (int nt = 0; nt < 8; nt++)
                    mma_f16(acc[m2][nt], a[m2], b[nt]);
        }
        __syncthreads();
    }

#pragma unroll
    for (int m2 = 0; m2 < 2; m2++) {
        int rl = wm * 32 + m2 * 16 + grp;
        int vA = v0 + rl;     if (vA >= VNT) vA = VNT - 1;
        int vB = v0 + rl + 8; if (vB >= VNT) vB = VNT - 1;
#pragma unroll
        for (int nt = 0; nt < 8; nt++) {
            int mcol = n0 + wn * 64 + nt * 8 + tig * 2;
            int jloc = wn * 16 + nt * 2 + (tig >> 1);
            int q = mcol & 3;
            float b0 = sBias[q * 32 + jloc], b1 = sBias[(q + 1) * 32 + jloc];
            *(float2*)&TWd[(size_t)vA * GG + mcol] =
                make_float2(acc[m2][nt][0] + b0, acc[m2][nt][1] + b1);
            *(float2*)&TWd[(size_t)vB * GG + mcol] =
                make_float2(acc[m2][nt][2] + b0, acc[m2][nt][3] + b1);
        }
    }
}

// ---------------- fused LSTM step: z = h@U (mma) + TW[e] lookup + gates -----
// grid (157, 4, 2), 256 thr = 8 warps (4M x 2N), C tile 128x128 of permuted z.
__global__ __launch_bounds__(256, 2) void lstm_step(
    const void* __restrict__ pe, int t)
{
    const int dir = blockIdx.z;
    const int s   = dir ? (TT - 1 - t) : t;
    const int cnt = g_cnt[s];
    const int p0  = blockIdx.x * 128;
    if (p0 >= cnt) return;
    const int n0  = blockIdx.y * 128;
    const int tid = threadIdx.x;

    __shared__ __align__(16) char smx[37888];
    __half (*AsH)[128][40] = (__half(*)[128][40])(smx);           // 20480 B
    __half (*BsH)[16][264] = (__half(*)[16][264])(smx + 20480);   // 16896 B
    int*   sE    = (int*)  (smx + 37376);                         // 512 B

    const __half* __restrict__ HoldH = g_Hh[dir][t & 1];
    __half* __restrict__ HnewH = g_Hh[dir][(t + 1) & 1];
    float* __restrict__ Cd   = g_Cst[dir];
    const __half* __restrict__ BuH = g_BuH[dir];
    const float* __restrict__ TWd = g_TW[dir];
    const int jcol0 = n0 >> 2;

    if (tid < 128) {
        int p = p0 + tid;
        if (p >= PP) p = PP - 1;
        int orig = g_perm[p];
        long long e;
        if (g_is64[0]) e = ((const long long*)pe)[(long long)orig * TT + s];
        else           e = ((const int*)pe)[orig * TT + s];
        sE[tid] = (int)e;
    }
    __syncthreads();

    const int warp = tid >> 5, lane = tid & 31;
    const int grp = lane >> 2, tig = lane & 3;
    const int wm = warp >> 1, wn = warp & 1;

    // ---- stage issuer: k-chunk ck (32 k of the h@U GEMM) into stage sb ----
    auto issue = [&](int ck, int sb) {
#pragma unroll
        for (int it = 0; it < 2; it++) {
            int idx = tid + it * 256;
            int r = idx >> 2, kh = (idx & 3) * 8;
            int p = p0 + r;
            if (p >= PP) p = PP - 1;
            cpa16(&AsH[sb][r][kh], &HoldH[(size_t)p * HH + ck * 32 + kh]);
        }
#pragma unroll
        for (int it = 0; it < 2; it++) {
            int idx = tid + it * 256;
            int k2 = idx >> 5, h8 = (idx & 31) * 8;
            cpa16(&BsH[sb][k2][h8],
                  &BuH[(size_t)(ck * 16 + k2) * 1024 + n0 * 2 + h8]);
        }
    };

    float acc[2][8][4];
#pragma unroll
    for (int m2 = 0; m2 < 2; m2++)
#pragma unroll
        for (int nt = 0; nt < 8; nt++)
#pragma unroll
            for (int q = 0; q < 4; q++) acc[m2][nt][q] = 0.f;

    issue(0, 0);
    cpa_commit();

    for (int ck = 0; ck < 4; ck++) {
        const int sb = ck & 1;
        if (ck < 3) {
            issue(ck + 1, sb ^ 1);
            cpa_commit();
            asm volatile("cp.async.wait_group 1;" ::: "memory");
        } else {
            asm volatile("cp.async.wait_group 0;" ::: "memory");
        }
        __syncthreads();

#pragma unroll
        for (int km = 0; km < 2; km++) {
            const int kb = km * 16;
            unsigned a[2][4], b[8][2];
#pragma unroll
            for (int m2 = 0; m2 < 2; m2++) {
                int rb = wm * 32 + m2 * 16;
                a[m2][0] = *(const unsigned*)&AsH[sb][rb + grp][kb + 2 * tig];
                a[m2][1] = *(const unsigned*)&AsH[sb][rb + grp + 8][kb + 2 * tig];
                a[m2][2] = *(const unsigned*)&AsH[sb][rb + grp][kb + 2 * tig + 8];
                a[m2][3] = *(const unsigned*)&AsH[sb][rb + grp + 8][kb + 2 * tig + 8];
            }
#pragma unroll
            for (int nt = 0; nt < 8; nt++) {
                int cb = wn * 64 + nt * 8 + grp;
                b[nt][0] = *(const unsigned*)&BsH[sb][km * 8 + tig][cb * 2];
                b[nt][1] = *(const unsigned*)&BsH[sb][km * 8 + tig + 4][cb * 2];
            }
#pragma unroll
            for (int m2 = 0; m2 < 2; m2++)
#pragma unroll
                for (int nt = 0; nt < 8; nt++)
                    mma_f16(acc[m2][nt], a[m2], b[nt]);
        }
        __syncthreads();
    }

    // ---- add TW[e] (x@W + bias) in fragment layout ----
#pragma unroll
    for (int m2 = 0; m2 < 2; m2++) {
        int rlA = wm * 32 + m2 * 16 + grp;
        size_t eA = (size_t)sE[rlA] * GG;
        size_t eB = (size_t)sE[rlA + 8] * GG;
#pragma unroll
        for (int nt = 0; nt < 8; nt++) {
            int mcol = n0 + wn * 64 + nt * 8 + tig * 2;
            float2 tA = *(const float2*)&TWd[eA + mcol];
            float2 tB = *(const float2*)&TWd[eB + mcol];
            acc[m2][nt][0] += tA.x; acc[m2][nt][1] += tA.y;
            acc[m2][nt][2] += tB.x; acc[m2][nt][3] += tB.y;
        }
    }

    // ---- fused gate epilogue, smem-staged coalesced state I/O ----
    float (*Cs)[36] = (float(*)[36])(smx);             // alias staging region
    float (*Hs)[36] = (float(*)[36])(smx + 18432);

    int nact = cnt - p0;
    if (nact > 128) nact = 128;
#pragma unroll
    for (int it = 0; it < 4; it++) {
        int i4 = tid + it * 256;
        int r = i4 >> 3, c4 = (i4 & 7) * 4;
        if (r < nact)
            *(float4*)&Cs[r][c4] =
                *(const float4*)&Cd[(size_t)(p0 + r) * HH + jcol0 + c4];
    }
    __syncthreads();

#pragma unroll
    for (int m2 = 0; m2 < 2; m2++) {
        int rl = wm * 32 + m2 * 16 + grp;
#pragma unroll
        for (int nt = 0; nt < 8; nt++) {
            float c0 = acc[m2][nt][0], c1 = acc[m2][nt][1];
            float c2 = acc[m2][nt][2], c3 = acc[m2][nt][3];
            float s0 = (tig & 1) ? c0 : c2;
            float s1 = (tig & 1) ? c1 : c3;
            float r0 = __shfl_xor_sync(0xffffffff, s0, 1);
            float r1 = __shfl_xor_sync(0xffffffff, s1, 1);
            int rr; float zi, zf, zg, zo;
            if ((tig & 1) == 0) { rr = rl;     zi = c0; zf = c1; zg = r0; zo = r1; }
            else                { rr = rl + 8; zi = r0; zf = r1; zg = c2; zo = c3; }
            int jl = wn * 16 + nt * 2 + (tig >> 1);
            if (rr < nact) {
                float ig = sigfast(zi), fg = sigfast(zf);
                float gg = tanhfast(zg), og = sigfast(zo);
                float c  = Cs[rr][jl];
                float cn = fg * c + ig * gg;
                Cs[rr][jl] = cn;
                Hs[rr][jl] = og * tanhfast(cn);
            }
        }
    }
    __syncthreads();

    // coalesced write-out: C fp32, H fp16 (converted here)
#pragma unroll
    for (int it = 0; it < 4; it++) {
        int i4 = tid + it * 256;
        int r = i4 >> 3, c4 = (i4 & 7) * 4;
        if (r < nact)
            *(float4*)&Cd[(size_t)(p0 + r) * HH + jcol0 + c4] =
                *(const float4*)&Cs[r][c4];
    }
#pragma unroll
    for (int it = 0; it < 2; it++) {
        int i8 = tid + it * 256;
        int r = i8 >> 2, c8 = (i8 & 3) * 8;
        if (r < nact) {
            float4 v0 = *(const float4*)&Hs[r][c8];
            float4 v1 = *(const float4*)&Hs[r][c8 + 4];
            __half2 hh[4];
            hh[0] = __floats2half2_rn(v0.x, v0.y);
            hh[1] = __floats2half2_rn(v0.z, v0.w);
            hh[2] = __floats2half2_rn(v1.x, v1.y);
            hh[3] = __floats2half2_rn(v1.z, v1.w);
            *(uint4*)&HnewH[(size_t)(p0 + r) * HH + jcol0 + c8] = *(uint4*)hh;
        }
    }
}

// ---------------- proj GEMM (fp16 mma): full = [leaf|h_f|h_b] @ proj --------
__global__ __launch_bounds__(256, 2) void proj_mma(
    const void* __restrict__ li, const float* __restrict__ att,
    const int* __restrict__ lens)
{
    const int p0 = blockIdx.x * 128;
    const int tid = threadIdx.x;
    __shared__ __align__(16) __half AsH[128][40];
    __shared__ __align__(16) __half BsH[16][264];
    __shared__ int   sL[128][2];
    __shared__ int   sBuf[128];
    __shared__ float sAtt[128];

    {
        int r = tid >> 1, which = tid & 1;
        int p = p0 + r;
        if (p >= PP) p = PP - 1;
        int orig = g_perm[p];
        long long v;
        if (g_is64[1]) v = ((const long long*)li)[(long long)orig * 2 + which];
        else           v = ((const int*)li)[orig * 2 + which];
        sL[r][which] = (int)v;
    }
    if (tid < 128) {
        int p = p0 + tid;
        if (p >= PP) p = PP - 1;
        int L = lens[g_perm[p]];
        if (L < 0) L = 0;
        sBuf[tid] = L & 1;
        sAtt[tid] = att[tid];
    }
    __syncthreads();

    const int warp = tid >> 5, lane = tid & 31;
    const int grp = lane >> 2, tig = lane & 3;
    const int wm = warp >> 1, wn = warp & 1;

    float acc[2][8][4];
#pragma unroll
    for (int mt = 0; mt < 2; mt++)
#pragma unroll
        for (int nt = 0; nt < 8; nt++)
#pragma unroll
            for (int q = 0; q < 4; q++) acc[mt][nt][q] = 0.f;

    for (int ck = 0; ck < 12; ck++) {      // K = 384
        const int k0 = ck * 32;
#pragma unroll
        for (int it = 0; it < 2; it++) {
            int idx = tid + it * 256;
            int r = idx >> 2, h8 = (idx & 3) * 8;
            int gk = k0 + h8;
            int p = p0 + r;
            if (p >= PP) p = PP - 1;
            const __half* src;
            if (gk < 64)       src = &g_leafH[(size_t)sL[r][0] * EE + gk];
            else if (gk < 128) src = &g_leafH[(size_t)sL[r][1] * EE + (gk - 64)];
            else if (gk < 256) src = &g_Hh[0][sBuf[r]][(size_t)p * HH + (gk - 128)];
            else               src = &g_Hh[1][0][(size_t)p * HH + (gk - 256)];
            *(uint4*)&AsH[r][h8] = *(const uint4*)src;
        }
#pragma unroll
        for (int it = 0; it < 2; it++) {
            int idx = tid + it * 256;
            int k2 = idx >> 5, h8 = (idx & 31) * 8;
            *(uint4*)&BsH[k2][h8] =
                *(const uint4*)&g_projH[(size_t)(ck * 16 + k2) * 256 + h8];
        }
        __syncthreads();

#pragma unroll
        for (int km = 0; km < 2; km++) {
            const int kb = km * 16;
            unsigned a[2][4], b[8][2];
#pragma unroll
            for (int mt = 0; mt < 2; mt++) {
                int rb = wm * 32 + mt * 16;
                a[mt][0] = *(const unsigned*)&AsH[rb + grp][kb + 2 * tig];
                a[mt][1] = *(const unsigned*)&AsH[rb + grp + 8][kb + 2 * tig];
                a[mt][2] = *(const unsigned*)&AsH[rb + grp][kb + 2 * tig + 8];
                a[mt][3] = *(const unsigned*)&AsH[rb + grp + 8][kb + 2 * tig + 8];
            }
#pragma unroll
            for (int nt = 0; nt < 8; nt++) {
                int cb = wn * 64 + nt * 8 + grp;
                b[nt][0] = *(const unsigned*)&BsH[km * 8 + tig][cb * 2];
                b[nt][1] = *(const unsigned*)&BsH[km * 8 + tig + 4][cb * 2];
            }
#pragma unroll
            for (int mt = 0; mt < 2; mt++)
#pragma unroll
                for (int nt = 0; nt < 8; nt++)
                    mma_f16(acc[mt][nt], a[mt], b[nt]);
        }
        __syncthreads();
    }

    // epilogue: write g_full + fused score dot (full . att)
    float loc[4] = {0.f, 0.f, 0.f, 0.f};
#pragma unroll
    for (int mt = 0; mt < 2; mt++) {
        int pr = p0 + wm * 32 + mt * 16 + grp;
#pragma unroll
        for (int nt = 0; nt < 8; nt++) {
            int col = wn * 64 + nt * 8 + tig * 2;
            float a0 = sAtt[col], a1 = sAtt[col + 1];
            loc[mt * 2 + 0] += acc[mt][nt][0] * a0 + acc[mt][nt][1] * a1;
            loc[mt * 2 + 1] += acc[mt][nt][2] * a0 + acc[mt][nt][3] * a1;
            if (pr < PP)
                *(float2*)&g_full[(size_t)pr * DPP + col] =
                    make_float2(acc[mt][nt][0], acc[mt][nt][1]);
            if (pr + 8 < PP)
                *(float2*)&g_full[(size_t)(pr + 8) * DPP + col] =
                    make_float2(acc[mt][nt][2], acc[mt][nt][3]);
        }
    }
#pragma unroll
    for (int q = 0; q < 4; q++) {
        loc[q] += __shfl_xor_sync(0xffffffff, loc[q], 1);
        loc[q] += __shfl_xor_sync(0xffffffff, loc[q], 2);
    }
    if (tig == 0) {
#pragma unroll
        for (int mt = 0; mt < 2; mt++) {
            int pr = p0 + wm * 32 + mt * 16 + grp;
            if (pr < PP)     atomicAdd(&g_scores[pr], loc[mt * 2 + 0]);
            if (pr + 8 < PP) atomicAdd(&g_scores[pr + 8], loc[mt * 2 + 1]);
        }
    }
}

// ---------------- segment softmax + weighted accumulation ------------------
__global__ void seg_max_k(const int* __restrict__ seg) {
    int p = blockIdx.x * 256 + threadIdx.x;
    if (p < PP) atomicMax(&g_mxe[seg[g_perm[p]]], encf(g_scores[p]));
}
__global__ void seg_den_k(const int* __restrict__ seg) {
    int p = blockIdx.x * 256 + threadIdx.x;
    if (p < PP) {
        int s = seg[g_perm[p]];
        atomicAdd(&g_den[s], __expf(g_scores[p] - decf(g_mxe[s])));
    }
}
__global__ void seg_out_k(const int* __restrict__ seg, float* __restrict__ out) {
    int idx = blockIdx.x * 256 + threadIdx.x;
    if (idx < PP * DPP) {
        int p = idx >> 7, j = idx & 127;
        int s = seg[g_perm[p]];
        float w = __expf(g_scores[p] - decf(g_mxe[s])) / g_den[s];
        atomicAdd(&out[(size_t)s * DPP + j], w * g_full[idx]);
    }
}

// ---------------- launch ----------------------------------------------------
extern "C" void kernel_launch(void* const* d_in, const int* in_sizes, int n_in,
                              void* d_out, int out_size)
{
    (void)in_sizes; (void)n_in; (void)out_size;
    const float* leafE = (const float*)d_in[0];
    const float* emb   = (const float*)d_in[1];
    const float* Wf    = (const float*)d_in[2];
    const float* Uf    = (const float*)d_in[3];
    const float* bf    = (const float*)d_in[4];
    const float* Wb    = (const float*)d_in[5];
    const float* Ub    = (const float*)d_in[6];
    const float* bb    = (const float*)d_in[7];
    const float* proj  = (const float*)d_in[8];
    const float* att   = (const float*)d_in[9];
    const void*  pe    = d_in[10];
    const int*   lens  = (const int*)d_in[11];
    const void*  li    = d_in[12];
    const int*   seg   = (const int*)d_in[13];
    float* out = (float*)d_out;

    const long long initN = 4LL * PP * HH + PP + SS + (long long)SS * DPP + TT + 2;
    init_kernel<<<(unsigned)((initN + 255) / 256), 256>>>(pe, li, out);
    hist_k<<<(PP + 255) / 256, 256>>>(lens);
    scan_k<<<1, 32>>>();
    scatter_k<<<(PP + 255) / 256, 256>>>(lens);
    const long long brN = 4LL * 128 * GG + (long long)VNT * DD
                        + (long long)VLEAF * EE + 384 * DPP;
    bround_k<<<(unsigned)((brN + 255) / 256), 256>>>(Wf, Uf, Wb, Ub, emb, leafE, proj);

    dim3 twgrid((VNT + 127) / 128, 4, 2);
    tw_k<<<twgrid, 256>>>(bf, bb);

    dim3 ggrid((PP + 127) / 128, 4, 2);
    for (int t = 0; t < TT; t++) {
        lstm_step<<<ggrid, 256>>>(pe, t);
    }
    proj_mma<<<(PP + 127) / 128, 256>>>(li, att, lens);
    seg_max_k<<<(PP + 255) / 256, 256>>>(seg);
    seg_den_k<<<(PP + 255) / 256, 256>>>(seg);
    seg_out_k<<<(PP * DPP + 255) / 256, 256>>>(seg, out);
}